// round 14
// baseline (speedup 1.0000x reference)
#include <cuda_runtime.h>
#include <cuda_fp16.h>
#include <math.h>

// ---------------- problem constants ----------------
#define BB    8
#define NTOK  1025
#define SP    1024
#define FHW   32
#define DIMC  768
#define NKV   1536
#define HEADS 12
#define DH    64
#define NROT  32

// ---------------- scratch ----------------
__device__ __half g_xn[BB*NTOK*DIMC];
__device__ __half g_dw[BB*SP*DIMC];
__device__ float  g_pw[BB*SP*DIMC];
__device__ float  g_kv[BB*NTOK*NKV];
__device__ __half g_q [BB*NTOK*DIMC];
__device__ __half g_k [BB*NTOK*DIMC];
__device__ __half g_v [BB*NTOK*DIMC];
__device__ __half g_ao[BB*NTOK*DIMC];
__device__ __half g_pww[DIMC*DIMC];
__device__ __half g_kvw[NKV*DIMC];
__device__ __half g_oww[DIMC*DIMC];

#define CEXP 0.18033688011112042f   // 0.125 * log2(e)

// ---------------- helpers ----------------
__device__ __forceinline__ void mma16(float* c, const unsigned* a, const unsigned* b) {
    asm volatile(
        "mma.sync.aligned.m16n8k16.row.col.f32.f16.f16.f32 "
        "{%0,%1,%2,%3}, {%4,%5,%6,%7}, {%8,%9}, {%0,%1,%2,%3};"
        : "+f"(c[0]), "+f"(c[1]), "+f"(c[2]), "+f"(c[3])
        : "r"(a[0]), "r"(a[1]), "r"(a[2]), "r"(a[3]), "r"(b[0]), "r"(b[1]));
}
__device__ __forceinline__ void cp16(void* dst, const void* src, bool valid) {
    unsigned d = (unsigned)__cvta_generic_to_shared(dst);
    int sz = valid ? 16 : 0;
    asm volatile("cp.async.ca.shared.global [%0], [%1], 16, %2;\n"
                 :: "r"(d), "l"(src), "r"(sz));
}
__device__ __forceinline__ void cp_commit() {
    asm volatile("cp.async.commit_group;\n");
}
template<int N>
__device__ __forceinline__ void cp_waitg() {
    asm volatile("cp.async.wait_group %0;\n" :: "n"(N));
}
__device__ __forceinline__ void ldsm4t(unsigned& r0, unsigned& r1,
                                       unsigned& r2, unsigned& r3, const void* p) {
    unsigned a = (unsigned)__cvta_generic_to_shared(p);
    asm volatile("ldmatrix.sync.aligned.m8n8.x4.trans.shared.b16 {%0,%1,%2,%3}, [%4];"
                 : "=r"(r0), "=r"(r1), "=r"(r2), "=r"(r3) : "r"(a));
}
__device__ __forceinline__ unsigned packh2(float lo, float hi) {
    __half2 h = __floats2half2_rn(lo, hi);
    return *reinterpret_cast<unsigned*>(&h);
}

// ---------------- weight prep ----------------
__global__ void round_pw_kernel(const float* __restrict__ pw) {
    int i = blockIdx.x * 256 + threadIdx.x;
    if (i < DIMC*DIMC) g_pww[i] = __float2half_rn(pw[i]);
}
__global__ void transpose_w_kernel(const float* __restrict__ src,
                                   __half* __restrict__ dst, int K, int N) {
    __shared__ float tile[32][33];
    int n0 = blockIdx.x * 32, k0 = blockIdx.y * 32;
    int tx = threadIdx.x, ty = threadIdx.y;
    #pragma unroll
    for (int dy = ty; dy < 32; dy += 8)
        tile[dy][tx] = src[(size_t)(k0 + dy) * N + n0 + tx];
    __syncthreads();
    #pragma unroll
    for (int dy = ty; dy < 32; dy += 8)
        dst[(size_t)(n0 + dy) * K + k0 + tx] = __float2half_rn(tile[tx][dy]);
}

// ---------------- layernorm ----------------
__global__ void __launch_bounds__(192) ln_kernel(const float* __restrict__ x,
                                                 const float* __restrict__ gamma,
                                                 const float* __restrict__ beta) {
    int row = blockIdx.x;
    int t = threadIdx.x;
    const float4 v = ((const float4*)(x + (size_t)row * DIMC))[t];

    float s  = (v.x + v.y) + (v.z + v.w);
    float s2 = (v.x*v.x + v.y*v.y) + (v.z*v.z + v.w*v.w);

    int lane = t & 31, w = t >> 5;
    #pragma unroll
    for (int o = 16; o; o >>= 1) {
        s  += __shfl_xor_sync(0xffffffffu, s,  o);
        s2 += __shfl_xor_sync(0xffffffffu, s2, o);
    }
    __shared__ float shs[6], shs2[6];
    if (lane == 0) { shs[w] = s; shs2[w] = s2; }
    __syncthreads();
    if (t < 32) {
        float a  = (lane < 6) ? shs[lane]  : 0.f;
        float a2 = (lane < 6) ? shs2[lane] : 0.f;
        #pragma unroll
        for (int o = 4; o; o >>= 1) {
            a  += __shfl_xor_sync(0xffffffffu, a,  o);
            a2 += __shfl_xor_sync(0xffffffffu, a2, o);
        }
        if (lane == 0) { shs[0] = a; shs2[0] = a2; }
    }
    __syncthreads();
    float mu  = shs[0] * (1.f / DIMC);
    float var = shs2[0] * (1.f / DIMC) - mu * mu;
    float r = rsqrtf(var + 1e-5f);

    const float4 gm = ((const float4*)gamma)[t];
    const float4 bt = ((const float4*)beta)[t];
    uint2 st;
    st.x = packh2((v.x - mu) * r * gm.x + bt.x, (v.y - mu) * r * gm.y + bt.y);
    st.y = packh2((v.z - mu) * r * gm.z + bt.z, (v.w - mu) * r * gm.w + bt.w);
    ((uint2*)(g_xn + (size_t)row * DIMC))[t] = st;
}

// ---------------- depthwise 5x5 conv ----------------
__global__ void __launch_bounds__(256) dw_kernel2(const float* __restrict__ w) {
    __shared__ float S[12][36][16];
    __shared__ float Ws[16][25];
    int c0 = blockIdx.x * 16;
    int y0 = blockIdx.y * 8;
    int b  = blockIdx.z;
    int tid = threadIdx.x;
    const __half* xn_b = g_xn + ((size_t)b * NTOK + 1) * DIMC;

    for (int i = tid; i < 16 * 25; i += 256) {
        int c = i / 25, kk = i % 25;
        Ws[c][kk] = w[(c0 + c) * 25 + kk];
    }
    for (int i = tid; i < 12 * 36 * 16; i += 256) {
        int row = i / 576, rem = i % 576;
        int col = rem / 16, ch = rem % 16;
        int gy = y0 + row - 2, gx = col - 2;
        float v = 0.f;
        if (gy >= 0 && gy < FHW && gx >= 0 && gx < FHW)
            v = __half2float(xn_b[(size_t)(gy * 32 + gx) * DIMC + c0 + ch]);
        S[row][col][ch] = v;
    }
    __syncthreads();

    for (int k = 0; k < 16; k++) {
        int oi = k * 256 + tid;
        int oc = oi & 15;
        int ox = (oi >> 4) & 31;
        int oy = oi >> 9;
        float acc = 0.f;
        #pragma unroll
        for (int ky = 0; ky < 5; ky++)
            #pragma unroll
            for (int kx = 0; kx < 5; kx++)
                acc = fmaf(Ws[oc][ky * 5 + kx], S[oy + ky][ox + kx][oc], acc);
        g_dw[((size_t)b * SP + (y0 + oy) * 32 + ox) * DIMC + c0 + oc] = __float2half_rn(acc);
    }
}

// ---------------- fp16 MMA GEMM ----------------
template<bool HAS_BIAS>
__global__ void __launch_bounds__(256, 2)
hgemm(const __half* __restrict__ A, const __half* __restrict__ B,
      const float* __restrict__ bias, float* __restrict__ C,
      int M, int N, int K) {
    __shared__ __align__(16) __half As[2][128][32];
    __shared__ __align__(16) __half Bs[2][128][32];

    int tid = threadIdx.x;
    int lane = tid & 31, warp = tid >> 5;
    int wm = warp >> 2, wn = warp & 3;
    int g = lane >> 2, t4 = lane & 3;
    int bm = blockIdx.y * 128, bn = blockIdx.x * 128;

    int ar = tid >> 1, ak = (tid & 1) * 16;
    int asw = (ar & 2) ? 16 : 0;

    auto issue = [&](int st, int k0) {
        const __half* ga = A + (size_t)(bm + ar) * K + k0 + ak;
        bool av = (bm + ar) < M;
        cp16(&As[st][ar][ak ^ asw],       ga,     av);
        cp16(&As[st][ar][(ak + 8) ^ asw], ga + 8, av);
        const __half* gb = B + (size_t)(bn + ar) * K + k0 + ak;
        cp16(&Bs[st][ar][ak ^ asw],       gb,     true);
        cp16(&Bs[st][ar][(ak + 8) ^ asw], gb + 8, true);
    };

    float acc[4][4][4];
    #pragma unroll
    for (int i = 0; i < 4; i++)
        #pragma unroll
        for (int j = 0; j < 4; j++)
            #pragma unroll
            for (int r = 0; r < 4; r++) acc[i][j][r] = 0.f;

    issue(0, 0);
    cp_commit();

    int fsw = (g & 2) ? 16 : 0;
    int NT = K >> 5;
    for (int t = 0; t < NT; t++) {
        if (t > 0) __syncthreads();
        if (t + 1 < NT) issue((t + 1) & 1, (t + 1) * 32);
        cp_commit();
        cp_waitg<1>();
        __syncthreads();
        int cur = t & 1;

        #pragma unroll
        for (int kb = 0; kb < 2; kb++) {
            int kc = (kb * 16 + 4 * t4) ^ fsw;
            unsigned af[4][4], bf[4][2];
            #pragma unroll
            for (int mi = 0; mi < 4; mi++) {
                int m0 = wm * 64 + mi * 16 + g;
                uint2 alo = *(const uint2*)&As[cur][m0][kc];
                uint2 ahi = *(const uint2*)&As[cur][m0 + 8][kc];
                af[mi][0] = alo.x; af[mi][1] = ahi.x;
                af[mi][2] = alo.y; af[mi][3] = ahi.y;
            }
            #pragma unroll
            for (int ni = 0; ni < 4; ni++) {
                int n0 = wn * 32 + ni * 8 + g;
                uint2 bb = *(const uint2*)&Bs[cur][n0][kc];
                bf[ni][0] = bb.x; bf[ni][1] = bb.y;
            }
            #pragma unroll
            for (int mi = 0; mi < 4; mi++)
                #pragma unroll
                for (int ni = 0; ni < 4; ni++)
                    mma16(acc[mi][ni], af[mi], bf[ni]);
        }
    }

    #pragma unroll
    for (int mi = 0; mi < 4; mi++) {
        int row0 = bm + wm * 64 + mi * 16 + g;
        int row1 = row0 + 8;
        #pragma unroll
        for (int ni = 0; ni < 4; ni++) {
            int col = bn + wn * 32 + ni * 8 + 2 * t4;
            float b0 = 0.f, b1 = 0.f;
            if (HAS_BIAS) { b0 = bias[col]; b1 = bias[col + 1]; }
            if (row0 < M) {
                float2 v = make_float2(acc[mi][ni][0] + b0, acc[mi][ni][1] + b1);
                *(float2*)(C + (size_t)row0 * N + col) = v;
            }
            if (row1 < M) {
                float2 v = make_float2(acc[mi][ni][2] + b0, acc[mi][ni][3] + b1);
                *(float2*)(C + (size_t)row1 * N + col) = v;
            }
        }
    }
}

// ---------------- q assembly + rope + kv split ----------------
__global__ void __launch_bounds__(128)
assemble_kernel(const float* __restrict__ sinp, const float* __restrict__ cosp) {
    int row = blockIdx.x;
    int b = row / NTOK, n = row % NTOK;
    const float* kvrow = g_kv + (size_t)row * NKV;
    unsigned* qd = (unsigned*)(g_q + (size_t)row * DIMC);
    unsigned* kd = (unsigned*)(g_k + (size_t)row * DIMC);
    unsigned* vd = (unsigned*)(g_v + (size_t)row * DIMC);

    if (n == 0) {
        const unsigned* xnrow = (const unsigned*)(g_xn + (size_t)row * DIMC);
        #pragma unroll
        for (int i = 0; i < 3; i++) {
            int p = threadIdx.x + i * 128;
            float2 kf = ((const float2*)kvrow)[p];
            float2 vf = ((const float2*)(kvrow + DIMC))[p];
            qd[p] = xnrow[p];
            kd[p] = packh2(kf.x, kf.y);
            vd[p] = packh2(vf.x, vf.y);
        }
        return;
    }

    const float* pwrow = g_pw + ((size_t)b * SP + (n - 1)) * DIMC;
    int pos = n - 1;
    #pragma unroll
    for (int i = 0; i < 3; i++) {
        int p = threadIdx.x + i * 128;
        int c = 2 * p;
        int d = c & 63;
        float2 qf = ((const float2*)pwrow)[p];
        float2 kf = ((const float2*)kvrow)[p];
        float2 vf = ((const float2*)(kvrow + DIMC))[p];
        if (d < NROT) {
            float2 cs = *(const float2*)(cosp + pos * NROT + d);
            float2 sn = *(const float2*)(sinp + pos * NROT + d);
            float q0 = qf.x * cs.x - qf.y * sn.x;
            float q1 = qf.y * cs.y + qf.x * sn.y;
            float k0 = kf.x * cs.x - kf.y * sn.x;
            float k1 = kf.y * cs.y + kf.x * sn.y;
            qf = make_float2(q0, q1);
            kf = make_float2(k0, k1);
        }
        qd[p] = packh2(qf.x, qf.y);
        kd[p] = packh2(kf.x, kf.y);
        vd[p] = packh2(vf.x, vf.y);
    }
}

// ---------------- fp16 tensor-core flash attention ----------------
#define KTILE 64
#define KSTRH 80
#define VSTRH 72

__global__ void __launch_bounds__(256, 2)
attn_mma_kernel(int bh0) {
    __shared__ __align__(16) __half Ks[2][KTILE][KSTRH];
    __shared__ __align__(16) __half Vs[2][KTILE][VSTRH];

    int bh = bh0 + blockIdx.x;
    int b = bh / HEADS, h = bh % HEADS;
    int qt0 = blockIdx.y * 128;
    int tid = threadIdx.x, lane = tid & 31, warp = tid >> 5;
    int g = lane >> 2, t4 = lane & 3;

    const __half* qb = g_q + ((size_t)b * NTOK) * DIMC + h * DH;
    const __half* kb = g_k + ((size_t)b * NTOK) * DIMC + h * DH;
    const __half* vb = g_v + ((size_t)b * NTOK) * DIMC + h * DH;

    int r0 = qt0 + warp * 16 + g;
    int r1 = r0 + 8;

    auto issue_kv = [&](int st, int kt0) {
        #pragma unroll
        for (int lp = 0; lp < 4; lp++) {
            int pos = tid + lp * 256;
            int mat = pos >> 9;
            int idx = pos & 511;
            int row = idx >> 3, seg = idx & 7;
            int key = kt0 + row;
            bool vld = key < NTOK;
            const __half* src = (mat ? vb : kb) + (size_t)key * DIMC + seg * 8;
            if (mat == 0) cp16(&Ks[st][row][seg * 8], src, vld);
            else          cp16(&Vs[st][row][seg * 8], src, vld);
        }
    };

    unsigned aq[4][4];
    #pragma unroll
    for (int kbk = 0; kbk < 4; kbk++) {
        uint2 lo = make_uint2(0u, 0u), hi = make_uint2(0u, 0u);
        if (r0 < NTOK) lo = *(const uint2*)(qb + (size_t)r0 * DIMC + kbk * 16 + 4 * t4);
        if (r1 < NTOK) hi = *(const uint2*)(qb + (size_t)r1 * DIMC + kbk * 16 + 4 * t4);
        aq[kbk][0] = lo.x; aq[kbk][1] = hi.x;
        aq[kbk][2] = lo.y; aq[kbk][3] = hi.y;
    }

    float o[8][4];
    #pragma unroll
    for (int i = 0; i < 8; i++)
        #pragma unroll
        for (int j = 0; j < 4; j++) o[i][j] = 0.f;
    float m0 = -1e30f, m1 = -1e30f, l0 = 0.f, l1 = 0.f;

    issue_kv(0, 0);
    cp_commit();

    const int NTILES = (NTOK + KTILE - 1) / KTILE;
    for (int it = 0; it < NTILES; it++) {
        __syncthreads();
        if (it + 1 < NTILES) issue_kv((it + 1) & 1, (it + 1) * KTILE);
        cp_commit();
        cp_waitg<1>();
        __syncthreads();
        int st = it & 1;
        int kt0 = it * KTILE;

        float sc[8][4];
        #pragma unroll
        for (int i = 0; i < 8; i++)
            #pragma unroll
            for (int j = 0; j < 4; j++) sc[i][j] = 0.f;

        #pragma unroll
        for (int kbk = 0; kbk < 4; kbk++) {
            #pragma unroll
            for (int ni = 0; ni < 8; ni++) {
                uint2 bb = *(const uint2*)&Ks[st][ni * 8 + g][kbk * 16 + 4 * t4];
                unsigned bf[2] = {bb.x, bb.y};
                mma16(sc[ni], aq[kbk], bf);
            }
        }

        if (kt0 + KTILE > NTOK) {
            #pragma unroll
            for (int ni = 0; ni < 8; ni++) {
                int key = kt0 + ni * 8 + 2 * t4;
                if (key     >= NTOK) { sc[ni][0] = -1e30f; sc[ni][2] = -1e30f; }
                if (key + 1 >= NTOK) { sc[ni][1] = -1e30f; sc[ni][3] = -1e30f; }
            }
        }

        float mx0 = -1e30f, mx1 = -1e30f;
        #pragma unroll
        for (int ni = 0; ni < 8; ni++) {
            mx0 = fmaxf(mx0, fmaxf(sc[ni][0], sc[ni][1]));
            mx1 = fmaxf(mx1, fmaxf(sc[ni][2], sc[ni][3]));
        }
        mx0 = fmaxf(mx0, __shfl_xor_sync(0xffffffffu, mx0, 1));
        mx0 = fmaxf(mx0, __shfl_xor_sync(0xffffffffu, mx0, 2));
        mx1 = fmaxf(mx1, __shfl_xor_sync(0xffffffffu, mx1, 1));
        mx1 = fmaxf(mx1, __shfl_xor_sync(0xffffffffu, mx1, 2));
        float nm0 = fmaxf(m0, mx0), nm1 = fmaxf(m1, mx1);
        float cor0 = exp2f((m0 - nm0) * CEXP), cor1 = exp2f((m1 - nm1) * CEXP);
        m0 = nm0; m1 = nm1;
        float mc0 = nm0 * CEXP, mc1 = nm1 * CEXP;

        float ps0 = 0.f, ps1 = 0.f;
        #pragma unroll
        for (int ni = 0; ni < 8; ni++) {
            sc[ni][0] = exp2f(fmaf(sc[ni][0], CEXP, -mc0)); ps0 += sc[ni][0];
            sc[ni][1] = exp2f(fmaf(sc[ni][1], CEXP, -mc0)); ps0 += sc[ni][1];
            sc[ni][2] = exp2f(fmaf(sc[ni][2], CEXP, -mc1)); ps1 += sc[ni][2];
            sc[ni][3] = exp2f(fmaf(sc[ni][3], CEXP, -mc1)); ps1 += sc[ni][3];
        }
        l0 = l0 * cor0 + ps0;
        l1 = l1 * cor1 + ps1;
        #pragma unroll
        for (int ni = 0; ni < 8; ni++) {
            o[ni][0] *= cor0; o[ni][1] *= cor0;
            o[ni][2] *= cor1; o[ni][3] *= cor1;
        }

        int vmat = lane >> 3, vr = lane & 7;
        #pragma unroll
        for (int kc = 0; kc < 4; kc++) {
            unsigned ap[4];
            ap[0] = packh2(sc[2*kc][0],   sc[2*kc][1]);
            ap[1] = packh2(sc[2*kc][2],   sc[2*kc][3]);
            ap[2] = packh2(sc[2*kc+1][0], sc[2*kc+1][1]);
            ap[3] = packh2(sc[2*kc+1][2], sc[2*kc+1][3]);
            #pragma unroll
            for (int np = 0; np < 4; np++) {
                unsigned b0, b1, b2, b3;
                const __half* vp = &Vs[st][kc * 16 + (vmat & 1) * 8 + vr]
                                      [np * 16 + (vmat >> 1) * 8];
                ldsm4t(b0, b1, b2, b3, vp);
                unsigned bfa[2] = {b0, b1}, bfb[2] = {b2, b3};
                mma16(o[np * 2],     ap, bfa);
                mma16(o[np * 2 + 1], ap, bfb);
            }
        }
    }

    l0 += __shfl_xor_sync(0xffffffffu, l0, 1);
    l0 += __shfl_xor_sync(0xffffffffu, l0, 2);
    l1 += __shfl_xor_sync(0xffffffffu, l1, 1);
    l1 += __shfl_xor_sync(0xffffffffu, l1, 2);
    float inv0 = 1.f / l0, inv1 = 1.f / l1;

    if (r0 < NTOK) {
        __half* op = g_ao + ((size_t)b * NTOK + r0) * DIMC + h * DH;
        #pragma unroll
        for (int ni = 0; ni < 8; ni++)
            *(unsigned*)(op + ni * 8 + 2 * t4) = packh2(o[ni][0] * inv0, o[ni][1] * inv0);
    }
    if (r1 < NTOK) {
        __half* op = g_ao + ((size_t)b * NTOK + r1) * DIMC + h * DH;
        #pragma unroll
        for (int ni = 0; ni < 8; ni++)
            *(unsigned*)(op + ni * 8 + 2 * t4) = packh2(o[ni][2] * inv1, o[ni][3] * inv1);
    }
}

// ---------------- launch (batch-pipelined attention + out gemm) -------------
extern "C" void kernel_launch(void* const* d_in, const int* in_sizes, int n_in,
                              void* d_out, int out_size) {
    const float* x     = (const float*)d_in[0];
    const float* sinp  = (const float*)d_in[1];
    const float* cosp  = (const float*)d_in[2];
    const float* ln_g  = (const float*)d_in[3];
    const float* ln_b  = (const float*)d_in[4];
    const float* dw_w  = (const float*)d_in[5];
    const float* pw_w  = (const float*)d_in[6];
    const float* kv_w  = (const float*)d_in[7];
    const float* out_w = (const float*)d_in[8];
    const float* out_b = (const float*)d_in[9];
    float* out = (float*)d_out;

    __half *p_dwh, *p_xnh, *p_aoh, *p_pww, *p_kvw, *p_oww;
    float *p_pw, *p_kv;
    cudaGetSymbolAddress((void**)&p_xnh, g_xn);
    cudaGetSymbolAddress((void**)&p_dwh, g_dw);
    cudaGetSymbolAddress((void**)&p_pw,  g_pw);
    cudaGetSymbolAddress((void**)&p_kv,  g_kv);
    cudaGetSymbolAddress((void**)&p_aoh, g_ao);
    cudaGetSymbolAddress((void**)&p_pww, g_pww);
    cudaGetSymbolAddress((void**)&p_kvw, g_kvw);
    cudaGetSymbolAddress((void**)&p_oww, g_oww);

    cudaStream_t s2;
    cudaEvent_t evFork, evLN, evKV, evAttnA, evOutA;
    cudaStreamCreateWithFlags(&s2, cudaStreamNonBlocking);
    cudaEventCreateWithFlags(&evFork,  cudaEventDisableTiming);
    cudaEventCreateWithFlags(&evLN,    cudaEventDisableTiming);
    cudaEventCreateWithFlags(&evKV,    cudaEventDisableTiming);
    cudaEventCreateWithFlags(&evAttnA, cudaEventDisableTiming);
    cudaEventCreateWithFlags(&evOutA,  cudaEventDisableTiming);

    // fork s2 from the capture (default) stream
    cudaEventRecord(evFork, 0);
    cudaStreamWaitEvent(s2, evFork, 0);

    // s2: weight prep (independent of LN)
    round_pw_kernel<<<(DIMC * DIMC + 255) / 256, 256, 0, s2>>>(pw_w);
    transpose_w_kernel<<<dim3(NKV / 32, DIMC / 32), dim3(32, 8), 0, s2>>>(kv_w, p_kvw, DIMC, NKV);
    transpose_w_kernel<<<dim3(DIMC / 32, DIMC / 32), dim3(32, 8), 0, s2>>>(out_w, p_oww, DIMC, DIMC);

    // default: LN
    ln_kernel<<<BB * NTOK, 192>>>(x, ln_g, ln_b);
    cudaEventRecord(evLN, 0);

    // s2: kv gemm after LN
    cudaStreamWaitEvent(s2, evLN, 0);
    hgemm<false><<<dim3(NKV / 128, (BB * NTOK + 127) / 128), 256, 0, s2>>>(
        p_xnh, p_kvw, nullptr, p_kv, BB * NTOK, NKV, DIMC);
    cudaEventRecord(evKV, s2);

    // default: dw -> pw gemm (concurrent with kv gemm)
    dw_kernel2<<<dim3(DIMC / 16, 4, BB), 256>>>(dw_w);
    hgemm<false><<<dim3(DIMC / 128, (BB * SP) / 128), 256>>>(
        p_dwh, p_pww, nullptr, p_pw, BB * SP, DIMC, DIMC);

    // join: assemble needs pw (default) + kv (s2)
    cudaStreamWaitEvent(0, evKV, 0);
    assemble_kernel<<<BB * NTOK, 128>>>(sinp, cosp);

    // attention half A (batches 0..3)
    attn_mma_kernel<<<dim3((BB / 2) * HEADS, 9), 256>>>(0);
    cudaEventRecord(evAttnA, 0);

    // attention half B (batches 4..7) on default
    attn_mma_kernel<<<dim3((BB / 2) * HEADS, 9), 256>>>((BB / 2) * HEADS);

    // s2: out-gemm for rows of batches 0..3, concurrent with attnB
    const int MHALF = (BB / 2) * NTOK;          // 4100
    cudaStreamWaitEvent(s2, evAttnA, 0);
    hgemm<true><<<dim3(DIMC / 128, (MHALF + 127) / 128), 256, 0, s2>>>(
        p_aoh, p_oww, out_b, out, MHALF, DIMC, DIMC);
    cudaEventRecord(evOutA, s2);

    // default: out-gemm for batches 4..7 after attnB
    hgemm<true><<<dim3(DIMC / 128, (MHALF + 127) / 128), 256>>>(
        p_aoh + (size_t)MHALF * DIMC, p_oww, out_b, out + (size_t)MHALF * DIMC,
        MHALF, DIMC, DIMC);

    // join s2 back before return
    cudaStreamWaitEvent(0, evOutA, 0);

    cudaEventDestroy(evFork);
    cudaEventDestroy(evLN);
    cudaEventDestroy(evKV);
    cudaEventDestroy(evAttnA);
    cudaEventDestroy(evOutA);
    cudaStreamDestroy(s2);
}

// round 15
// speedup vs baseline: 1.0193x; 1.0193x over previous
#include <cuda_runtime.h>
#include <cuda_fp16.h>
#include <math.h>

// ---------------- problem constants ----------------
#define BB    8
#define NTOK  1025
#define SP    1024
#define FHW   32
#define DIMC  768
#define NKV   1536
#define HEADS 12
#define DH    64
#define NROT  32

// ---------------- scratch ----------------
__device__ __half g_xn[BB*NTOK*DIMC];
__device__ __half g_dw[BB*SP*DIMC];
__device__ float  g_pw[BB*SP*DIMC];
__device__ float  g_kv[BB*NTOK*NKV];
__device__ __half g_q [BB*NTOK*DIMC];
__device__ __half g_k [BB*NTOK*DIMC];
__device__ __half g_v [BB*NTOK*DIMC];
__device__ __half g_ao[BB*NTOK*DIMC];
__device__ __half g_pww[DIMC*DIMC];
__device__ __half g_kvw[NKV*DIMC];
__device__ __half g_oww[DIMC*DIMC];

#define CEXP 0.18033688011112042f   // 0.125 * log2(e)

// ---------------- helpers ----------------
__device__ __forceinline__ void mma16(float* c, const unsigned* a, const unsigned* b) {
    asm volatile(
        "mma.sync.aligned.m16n8k16.row.col.f32.f16.f16.f32 "
        "{%0,%1,%2,%3}, {%4,%5,%6,%7}, {%8,%9}, {%0,%1,%2,%3};"
        : "+f"(c[0]), "+f"(c[1]), "+f"(c[2]), "+f"(c[3])
        : "r"(a[0]), "r"(a[1]), "r"(a[2]), "r"(a[3]), "r"(b[0]), "r"(b[1]));
}
__device__ __forceinline__ void cp16(void* dst, const void* src, bool valid) {
    unsigned d = (unsigned)__cvta_generic_to_shared(dst);
    int sz = valid ? 16 : 0;
    asm volatile("cp.async.ca.shared.global [%0], [%1], 16, %2;\n"
                 :: "r"(d), "l"(src), "r"(sz));
}
__device__ __forceinline__ void cp_commit() {
    asm volatile("cp.async.commit_group;\n");
}
template<int N>
__device__ __forceinline__ void cp_waitg() {
    asm volatile("cp.async.wait_group %0;\n" :: "n"(N));
}
__device__ __forceinline__ void ldsm4t(unsigned& r0, unsigned& r1,
                                       unsigned& r2, unsigned& r3, const void* p) {
    unsigned a = (unsigned)__cvta_generic_to_shared(p);
    asm volatile("ldmatrix.sync.aligned.m8n8.x4.trans.shared.b16 {%0,%1,%2,%3}, [%4];"
                 : "=r"(r0), "=r"(r1), "=r"(r2), "=r"(r3) : "r"(a));
}
__device__ __forceinline__ void ldsm2t(unsigned& r0, unsigned& r1, const void* p) {
    unsigned a = (unsigned)__cvta_generic_to_shared(p);
    asm volatile("ldmatrix.sync.aligned.m8n8.x2.trans.shared.b16 {%0,%1}, [%2];"
                 : "=r"(r0), "=r"(r1) : "r"(a));
}
__device__ __forceinline__ unsigned packh2(float lo, float hi) {
    __half2 h = __floats2half2_rn(lo, hi);
    return *reinterpret_cast<unsigned*>(&h);
}
__device__ __forceinline__ unsigned ex2h2(unsigned v) {
    unsigned r;
    asm("ex2.approx.f16x2 %0, %1;" : "=r"(r) : "r"(v));
    return r;
}

// ---------------- weight prep ----------------
__global__ void round_pw_kernel(const float* __restrict__ pw) {
    int i = blockIdx.x * 256 + threadIdx.x;
    if (i < DIMC*DIMC) g_pww[i] = __float2half_rn(pw[i]);
}
__global__ void transpose_w_kernel(const float* __restrict__ src,
                                   __half* __restrict__ dst, int K, int N) {
    __shared__ float tile[32][33];
    int n0 = blockIdx.x * 32, k0 = blockIdx.y * 32;
    int tx = threadIdx.x, ty = threadIdx.y;
    #pragma unroll
    for (int dy = ty; dy < 32; dy += 8)
        tile[dy][tx] = src[(size_t)(k0 + dy) * N + n0 + tx];
    __syncthreads();
    #pragma unroll
    for (int dy = ty; dy < 32; dy += 8)
        dst[(size_t)(n0 + dy) * K + k0 + tx] = __float2half_rn(tile[tx][dy]);
}

// ---------------- layernorm ----------------
__global__ void __launch_bounds__(192) ln_kernel(const float* __restrict__ x,
                                                 const float* __restrict__ gamma,
                                                 const float* __restrict__ beta) {
    int row = blockIdx.x;
    int t = threadIdx.x;
    const float4 v = ((const float4*)(x + (size_t)row * DIMC))[t];

    float s  = (v.x + v.y) + (v.z + v.w);
    float s2 = (v.x*v.x + v.y*v.y) + (v.z*v.z + v.w*v.w);

    int lane = t & 31, w = t >> 5;
    #pragma unroll
    for (int o = 16; o; o >>= 1) {
        s  += __shfl_xor_sync(0xffffffffu, s,  o);
        s2 += __shfl_xor_sync(0xffffffffu, s2, o);
    }
    __shared__ float shs[6], shs2[6];
    if (lane == 0) { shs[w] = s; shs2[w] = s2; }
    __syncthreads();
    if (t < 32) {
        float a  = (lane < 6) ? shs[lane]  : 0.f;
        float a2 = (lane < 6) ? shs2[lane] : 0.f;
        #pragma unroll
        for (int o = 4; o; o >>= 1) {
            a  += __shfl_xor_sync(0xffffffffu, a,  o);
            a2 += __shfl_xor_sync(0xffffffffu, a2, o);
        }
        if (lane == 0) { shs[0] = a; shs2[0] = a2; }
    }
    __syncthreads();
    float mu  = shs[0] * (1.f / DIMC);
    float var = shs2[0] * (1.f / DIMC) - mu * mu;
    float r = rsqrtf(var + 1e-5f);

    const float4 gm = ((const float4*)gamma)[t];
    const float4 bt = ((const float4*)beta)[t];
    uint2 st;
    st.x = packh2((v.x - mu) * r * gm.x + bt.x, (v.y - mu) * r * gm.y + bt.y);
    st.y = packh2((v.z - mu) * r * gm.z + bt.z, (v.w - mu) * r * gm.w + bt.w);
    ((uint2*)(g_xn + (size_t)row * DIMC))[t] = st;
}

// ---------------- depthwise 5x5 conv ----------------
__global__ void __launch_bounds__(256) dw_kernel2(const float* __restrict__ w) {
    __shared__ float S[12][36][16];
    __shared__ float Ws[16][25];
    int c0 = blockIdx.x * 16;
    int y0 = blockIdx.y * 8;
    int b  = blockIdx.z;
    int tid = threadIdx.x;
    const __half* xn_b = g_xn + ((size_t)b * NTOK + 1) * DIMC;

    for (int i = tid; i < 16 * 25; i += 256) {
        int c = i / 25, kk = i % 25;
        Ws[c][kk] = w[(c0 + c) * 25 + kk];
    }
    for (int i = tid; i < 12 * 36 * 16; i += 256) {
        int row = i / 576, rem = i % 576;
        int col = rem / 16, ch = rem % 16;
        int gy = y0 + row - 2, gx = col - 2;
        float v = 0.f;
        if (gy >= 0 && gy < FHW && gx >= 0 && gx < FHW)
            v = __half2float(xn_b[(size_t)(gy * 32 + gx) * DIMC + c0 + ch]);
        S[row][col][ch] = v;
    }
    __syncthreads();

    for (int k = 0; k < 16; k++) {
        int oi = k * 256 + tid;
        int oc = oi & 15;
        int ox = (oi >> 4) & 31;
        int oy = oi >> 9;
        float acc = 0.f;
        #pragma unroll
        for (int ky = 0; ky < 5; ky++)
            #pragma unroll
            for (int kx = 0; kx < 5; kx++)
                acc = fmaf(Ws[oc][ky * 5 + kx], S[oy + ky][ox + kx][oc], acc);
        g_dw[((size_t)b * SP + (y0 + oy) * 32 + ox) * DIMC + c0 + oc] = __float2half_rn(acc);
    }
}

// ---------------- fp16 MMA GEMM ----------------
template<bool HAS_BIAS>
__global__ void __launch_bounds__(256, 2)
hgemm(const __half* __restrict__ A, const __half* __restrict__ B,
      const float* __restrict__ bias, float* __restrict__ C,
      int M, int N, int K) {
    __shared__ __align__(16) __half As[2][128][32];
    __shared__ __align__(16) __half Bs[2][128][32];

    int tid = threadIdx.x;
    int lane = tid & 31, warp = tid >> 5;
    int wm = warp >> 2, wn = warp & 3;
    int g = lane >> 2, t4 = lane & 3;
    int bm = blockIdx.y * 128, bn = blockIdx.x * 128;

    int ar = tid >> 1, ak = (tid & 1) * 16;
    int asw = (ar & 2) ? 16 : 0;

    auto issue = [&](int st, int k0) {
        const __half* ga = A + (size_t)(bm + ar) * K + k0 + ak;
        bool av = (bm + ar) < M;
        cp16(&As[st][ar][ak ^ asw],       ga,     av);
        cp16(&As[st][ar][(ak + 8) ^ asw], ga + 8, av);
        const __half* gb = B + (size_t)(bn + ar) * K + k0 + ak;
        cp16(&Bs[st][ar][ak ^ asw],       gb,     true);
        cp16(&Bs[st][ar][(ak + 8) ^ asw], gb + 8, true);
    };

    float acc[4][4][4];
    #pragma unroll
    for (int i = 0; i < 4; i++)
        #pragma unroll
        for (int j = 0; j < 4; j++)
            #pragma unroll
            for (int r = 0; r < 4; r++) acc[i][j][r] = 0.f;

    issue(0, 0);
    cp_commit();

    int fsw = (g & 2) ? 16 : 0;
    int NT = K >> 5;
    for (int t = 0; t < NT; t++) {
        if (t > 0) __syncthreads();
        if (t + 1 < NT) issue((t + 1) & 1, (t + 1) * 32);
        cp_commit();
        cp_waitg<1>();
        __syncthreads();
        int cur = t & 1;

        #pragma unroll
        for (int kb = 0; kb < 2; kb++) {
            int kc = (kb * 16 + 4 * t4) ^ fsw;
            unsigned af[4][4], bf[4][2];
            #pragma unroll
            for (int mi = 0; mi < 4; mi++) {
                int m0 = wm * 64 + mi * 16 + g;
                uint2 alo = *(const uint2*)&As[cur][m0][kc];
                uint2 ahi = *(const uint2*)&As[cur][m0 + 8][kc];
                af[mi][0] = alo.x; af[mi][1] = ahi.x;
                af[mi][2] = alo.y; af[mi][3] = ahi.y;
            }
            #pragma unroll
            for (int ni = 0; ni < 4; ni++) {
                int n0 = wn * 32 + ni * 8 + g;
                uint2 bb = *(const uint2*)&Bs[cur][n0][kc];
                bf[ni][0] = bb.x; bf[ni][1] = bb.y;
            }
            #pragma unroll
            for (int mi = 0; mi < 4; mi++)
                #pragma unroll
                for (int ni = 0; ni < 4; ni++)
                    mma16(acc[mi][ni], af[mi], bf[ni]);
        }
    }

    #pragma unroll
    for (int mi = 0; mi < 4; mi++) {
        int row0 = bm + wm * 64 + mi * 16 + g;
        int row1 = row0 + 8;
        #pragma unroll
        for (int ni = 0; ni < 4; ni++) {
            int col = bn + wn * 32 + ni * 8 + 2 * t4;
            float b0 = 0.f, b1 = 0.f;
            if (HAS_BIAS) { b0 = bias[col]; b1 = bias[col + 1]; }
            if (row0 < M) {
                float2 v = make_float2(acc[mi][ni][0] + b0, acc[mi][ni][1] + b1);
                *(float2*)(C + (size_t)row0 * N + col) = v;
            }
            if (row1 < M) {
                float2 v = make_float2(acc[mi][ni][2] + b0, acc[mi][ni][3] + b1);
                *(float2*)(C + (size_t)row1 * N + col) = v;
            }
        }
    }
}

// ---------------- q assembly + rope + kv split ----------------
__global__ void __launch_bounds__(128)
assemble_kernel(const float* __restrict__ sinp, const float* __restrict__ cosp) {
    int row = blockIdx.x;
    int b = row / NTOK, n = row % NTOK;
    const float* kvrow = g_kv + (size_t)row * NKV;
    unsigned* qd = (unsigned*)(g_q + (size_t)row * DIMC);
    unsigned* kd = (unsigned*)(g_k + (size_t)row * DIMC);
    unsigned* vd = (unsigned*)(g_v + (size_t)row * DIMC);

    if (n == 0) {
        const unsigned* xnrow = (const unsigned*)(g_xn + (size_t)row * DIMC);
        #pragma unroll
        for (int i = 0; i < 3; i++) {
            int p = threadIdx.x + i * 128;
            float2 kf = ((const float2*)kvrow)[p];
            float2 vf = ((const float2*)(kvrow + DIMC))[p];
            qd[p] = xnrow[p];
            kd[p] = packh2(kf.x, kf.y);
            vd[p] = packh2(vf.x, vf.y);
        }
        return;
    }

    const float* pwrow = g_pw + ((size_t)b * SP + (n - 1)) * DIMC;
    int pos = n - 1;
    #pragma unroll
    for (int i = 0; i < 3; i++) {
        int p = threadIdx.x + i * 128;
        int c = 2 * p;
        int d = c & 63;
        float2 qf = ((const float2*)pwrow)[p];
        float2 kf = ((const float2*)kvrow)[p];
        float2 vf = ((const float2*)(kvrow + DIMC))[p];
        if (d < NROT) {
            float2 cs = *(const float2*)(cosp + pos * NROT + d);
            float2 sn = *(const float2*)(sinp + pos * NROT + d);
            float q0 = qf.x * cs.x - qf.y * sn.x;
            float q1 = qf.y * cs.y + qf.x * sn.y;
            float k0 = kf.x * cs.x - kf.y * sn.x;
            float k1 = kf.y * cs.y + kf.x * sn.y;
            qf = make_float2(q0, q1);
            kf = make_float2(k0, k1);
        }
        qd[p] = packh2(qf.x, qf.y);
        kd[p] = packh2(kf.x, kf.y);
        vd[p] = packh2(vf.x, vf.y);
    }
}

// ---------------- fp16 flash attention: f16x2 exp + ones-column l ----------
#define KTILE 64
#define KSTRH 80
#define VSTRH 72

__global__ void __launch_bounds__(256, 2)
attn_mma_kernel() {
    __shared__ __align__(16) __half Ks[2][KTILE][KSTRH];
    __shared__ __align__(16) __half Vs[2][KTILE][VSTRH];

    int bh = blockIdx.x;
    int b = bh / HEADS, h = bh % HEADS;
    int qt0 = blockIdx.y * 128;
    int tid = threadIdx.x, lane = tid & 31, warp = tid >> 5;
    int g = lane >> 2, t4 = lane & 3;

    const __half* qb = g_q + ((size_t)b * NTOK) * DIMC + h * DH;
    const __half* kb = g_k + ((size_t)b * NTOK) * DIMC + h * DH;
    const __half* vb = g_v + ((size_t)b * NTOK) * DIMC + h * DH;

    int r0 = qt0 + warp * 16 + g;
    int r1 = r0 + 8;

    auto issue_kv = [&](int st, int kt0) {
        #pragma unroll
        for (int lp = 0; lp < 4; lp++) {
            int pos = tid + lp * 256;
            int mat = pos >> 9;
            int idx = pos & 511;
            int row = idx >> 3, seg = idx & 7;
            int key = kt0 + row;
            bool vld = key < NTOK;
            const __half* src = (mat ? vb : kb) + (size_t)key * DIMC + seg * 8;
            if (mat == 0) cp16(&Ks[st][row][seg * 8], src, vld);
            else          cp16(&Vs[st][row][seg * 8], src, vld);
        }
    };

    // ones-column region: Vs[st][row][64]=1, [65..71]=0 (cp.async never touches cols>=64)
    for (int i = tid; i < 2 * KTILE; i += 256) {
        int st = i >> 6, row = i & 63;
        __half* p = &Vs[st][row][64];
        p[0] = __float2half(1.f);
        #pragma unroll
        for (int j = 1; j < 8; j++) p[j] = __float2half(0.f);
    }

    unsigned aq[4][4];
    #pragma unroll
    for (int kbk = 0; kbk < 4; kbk++) {
        uint2 lo = make_uint2(0u, 0u), hi = make_uint2(0u, 0u);
        if (r0 < NTOK) lo = *(const uint2*)(qb + (size_t)r0 * DIMC + kbk * 16 + 4 * t4);
        if (r1 < NTOK) hi = *(const uint2*)(qb + (size_t)r1 * DIMC + kbk * 16 + 4 * t4);
        aq[kbk][0] = lo.x; aq[kbk][1] = hi.x;
        aq[kbk][2] = lo.y; aq[kbk][3] = hi.y;
    }

    float o[8][4];
    #pragma unroll
    for (int i = 0; i < 8; i++)
        #pragma unroll
        for (int j = 0; j < 4; j++) o[i][j] = 0.f;
    float ol[4] = {0.f, 0.f, 0.f, 0.f};       // ones-column accumulator (l)
    float m0 = -1e30f, m1 = -1e30f;

    issue_kv(0, 0);
    cp_commit();

    const int NTILES = (NTOK + KTILE - 1) / KTILE;
    for (int it = 0; it < NTILES; it++) {
        __syncthreads();
        if (it + 1 < NTILES) issue_kv((it + 1) & 1, (it + 1) * KTILE);
        cp_commit();
        cp_waitg<1>();
        __syncthreads();
        int st = it & 1;
        int kt0 = it * KTILE;

        float sc[8][4];
        #pragma unroll
        for (int i = 0; i < 8; i++)
            #pragma unroll
            for (int j = 0; j < 4; j++) sc[i][j] = 0.f;

        #pragma unroll
        for (int kbk = 0; kbk < 4; kbk++) {
            #pragma unroll
            for (int ni = 0; ni < 8; ni++) {
                uint2 bb = *(const uint2*)&Ks[st][ni * 8 + g][kbk * 16 + 4 * t4];
                unsigned bf[2] = {bb.x, bb.y};
                mma16(sc[ni], aq[kbk], bf);
            }
        }

        if (kt0 + KTILE > NTOK) {
            #pragma unroll
            for (int ni = 0; ni < 8; ni++) {
                int key = kt0 + ni * 8 + 2 * t4;
                if (key     >= NTOK) { sc[ni][0] = -1e30f; sc[ni][2] = -1e30f; }
                if (key + 1 >= NTOK) { sc[ni][1] = -1e30f; sc[ni][3] = -1e30f; }
            }
        }

        // ---- online max (fp32) ----
        float mx0 = -1e30f, mx1 = -1e30f;
        #pragma unroll
        for (int ni = 0; ni < 8; ni++) {
            mx0 = fmaxf(mx0, fmaxf(sc[ni][0], sc[ni][1]));
            mx1 = fmaxf(mx1, fmaxf(sc[ni][2], sc[ni][3]));
        }
        mx0 = fmaxf(mx0, __shfl_xor_sync(0xffffffffu, mx0, 1));
        mx0 = fmaxf(mx0, __shfl_xor_sync(0xffffffffu, mx0, 2));
        mx1 = fmaxf(mx1, __shfl_xor_sync(0xffffffffu, mx1, 1));
        mx1 = fmaxf(mx1, __shfl_xor_sync(0xffffffffu, mx1, 2));
        float nm0 = fmaxf(m0, mx0), nm1 = fmaxf(m1, mx1);
        float cor0 = exp2f((m0 - nm0) * CEXP), cor1 = exp2f((m1 - nm1) * CEXP);
        m0 = nm0; m1 = nm1;
        float mc0 = nm0 * CEXP, mc1 = nm1 * CEXP;

        // ---- t = s*CEXP - m*CEXP (fp32, in place) ----
        #pragma unroll
        for (int ni = 0; ni < 8; ni++) {
            sc[ni][0] = fmaf(sc[ni][0], CEXP, -mc0);
            sc[ni][1] = fmaf(sc[ni][1], CEXP, -mc0);
            sc[ni][2] = fmaf(sc[ni][2], CEXP, -mc1);
            sc[ni][3] = fmaf(sc[ni][3], CEXP, -mc1);
        }

        // rescale o and ol
        #pragma unroll
        for (int ni = 0; ni < 8; ni++) {
            o[ni][0] *= cor0; o[ni][1] *= cor0;
            o[ni][2] *= cor1; o[ni][3] *= cor1;
        }
        ol[0] *= cor0; ol[1] *= cor0; ol[2] *= cor1; ol[3] *= cor1;

        // ---- P = ex2.f16x2 (pack pre-exp, exponentiate in half2) ----
        int vmat = lane >> 3, vr = lane & 7;
        #pragma unroll
        for (int kc = 0; kc < 4; kc++) {
            unsigned ap[4];
            ap[0] = ex2h2(packh2(sc[2*kc][0],   sc[2*kc][1]));
            ap[1] = ex2h2(packh2(sc[2*kc][2],   sc[2*kc][3]));
            ap[2] = ex2h2(packh2(sc[2*kc+1][0], sc[2*kc+1][1]));
            ap[3] = ex2h2(packh2(sc[2*kc+1][2], sc[2*kc+1][3]));
            #pragma unroll
            for (int np = 0; np < 4; np++) {
                unsigned b0, b1, b2, b3;
                const __half* vp = &Vs[st][kc * 16 + (vmat & 1) * 8 + vr]
                                      [np * 16 + (vmat >> 1) * 8];
                ldsm4t(b0, b1, b2, b3, vp);
                unsigned bfa[2] = {b0, b1}, bfb[2] = {b2, b3};
                mma16(o[np * 2],     ap, bfa);
                mma16(o[np * 2 + 1], ap, bfb);
            }
            // ones-column: l accumulation via tensor core (cols 64..71)
            {
                unsigned c0, c1;
                int lrow = kc * 16 + ((lane >> 3) & 1) * 8 + vr;   // lanes 0..15 matter
                ldsm2t(c0, c1, &Vs[st][lrow][64]);
                unsigned bfl[2] = {c0, c1};
                mma16(ol, ap, bfl);
            }
        }
    }

    // l lives in ol[0]/ol[2] of the quad lane with t4==0 (col 64)
    int qsrc = lane & ~3;
    float l0 = __shfl_sync(0xffffffffu, ol[0], qsrc);
    float l1 = __shfl_sync(0xffffffffu, ol[2], qsrc);
    float inv0 = 1.f / l0, inv1 = 1.f / l1;

    if (r0 < NTOK) {
        __half* op = g_ao + ((size_t)b * NTOK + r0) * DIMC + h * DH;
        #pragma unroll
        for (int ni = 0; ni < 8; ni++)
            *(unsigned*)(op + ni * 8 + 2 * t4) = packh2(o[ni][0] * inv0, o[ni][1] * inv0);
    }
    if (r1 < NTOK) {
        __half* op = g_ao + ((size_t)b * NTOK + r1) * DIMC + h * DH;
        #pragma unroll
        for (int ni = 0; ni < 8; ni++)
            *(unsigned*)(op + ni * 8 + 2 * t4) = packh2(o[ni][2] * inv1, o[ni][3] * inv1);
    }
}

// ---------------- launch ----------------
extern "C" void kernel_launch(void* const* d_in, const int* in_sizes, int n_in,
                              void* d_out, int out_size) {
    const float* x     = (const float*)d_in[0];
    const float* sinp  = (const float*)d_in[1];
    const float* cosp  = (const float*)d_in[2];
    const float* ln_g  = (const float*)d_in[3];
    const float* ln_b  = (const float*)d_in[4];
    const float* dw_w  = (const float*)d_in[5];
    const float* pw_w  = (const float*)d_in[6];
    const float* kv_w  = (const float*)d_in[7];
    const float* out_w = (const float*)d_in[8];
    const float* out_b = (const float*)d_in[9];
    float* out = (float*)d_out;

    __half *p_dwh, *p_xnh, *p_aoh, *p_pww, *p_kvw, *p_oww;
    float *p_pw, *p_kv;
    cudaGetSymbolAddress((void**)&p_xnh, g_xn);
    cudaGetSymbolAddress((void**)&p_dwh, g_dw);
    cudaGetSymbolAddress((void**)&p_pw,  g_pw);
    cudaGetSymbolAddress((void**)&p_kv,  g_kv);
    cudaGetSymbolAddress((void**)&p_aoh, g_ao);
    cudaGetSymbolAddress((void**)&p_pww, g_pww);
    cudaGetSymbolAddress((void**)&p_kvw, g_kvw);
    cudaGetSymbolAddress((void**)&p_oww, g_oww);

    cudaStream_t s2;
    cudaEvent_t evFork, evLN, evKV;
    cudaStreamCreateWithFlags(&s2, cudaStreamNonBlocking);
    cudaEventCreateWithFlags(&evFork, cudaEventDisableTiming);
    cudaEventCreateWithFlags(&evLN,   cudaEventDisableTiming);
    cudaEventCreateWithFlags(&evKV,   cudaEventDisableTiming);

    cudaEventRecord(evFork, 0);
    cudaStreamWaitEvent(s2, evFork, 0);

    round_pw_kernel<<<(DIMC * DIMC + 255) / 256, 256, 0, s2>>>(pw_w);
    transpose_w_kernel<<<dim3(NKV / 32, DIMC / 32), dim3(32, 8), 0, s2>>>(kv_w, p_kvw, DIMC, NKV);
    transpose_w_kernel<<<dim3(DIMC / 32, DIMC / 32), dim3(32, 8), 0, s2>>>(out_w, p_oww, DIMC, DIMC);

    ln_kernel<<<BB * NTOK, 192>>>(x, ln_g, ln_b);
    cudaEventRecord(evLN, 0);

    cudaStreamWaitEvent(s2, evLN, 0);
    hgemm<false><<<dim3(NKV / 128, (BB * NTOK + 127) / 128), 256, 0, s2>>>(
        p_xnh, p_kvw, nullptr, p_kv, BB * NTOK, NKV, DIMC);
    cudaEventRecord(evKV, s2);

    dw_kernel2<<<dim3(DIMC / 16, 4, BB), 256>>>(dw_w);
    hgemm<false><<<dim3(DIMC / 128, (BB * SP) / 128), 256>>>(
        p_dwh, p_pww, nullptr, p_pw, BB * SP, DIMC, DIMC);

    cudaStreamWaitEvent(0, evKV, 0);
    assemble_kernel<<<BB * NTOK, 128>>>(sinp, cosp);
    attn_mma_kernel<<<dim3(BB * HEADS, 9), 256>>>();
    hgemm<true><<<dim3(DIMC / 128, (BB * NTOK + 127) / 128), 256>>>(
        p_aoh, p_oww, out_b, out, BB * NTOK, DIMC, DIMC);

    cudaEventDestroy(evFork);
    cudaEventDestroy(evLN);
    cudaEventDestroy(evKV);
    cudaStreamDestroy(s2);
}